// round 16
// baseline (speedup 1.0000x reference)
#include <cuda_runtime.h>

// Problem constants
#define E_ 4
#define B_ 128
#define Q_ 900
#define C_ 256
#define H_ 16
#define QC_ (Q_ * C_)          // 230400
#define QC4_ (QC_ / 4)         // 57600 float4 per b

#define THR_ 128
#define NBLK_ 1024             // single wave: ceil(1024/148)=7 <= 8 (launch_bounds)

// Probs jobs: job j -> b = j>>5, e = (j&31)>>3, part = j&7. 4 jobs per block.
#define SPLIT_ 8
#define QCHUNK_ 113            // ceil(900/8)
#define NJOBS_ (E_ * B_ * SPLIT_)    // 4096
#define JOBS_PER_BLK_ (NJOBS_ / NBLK_) // 4

// Combine chunks: 640 float4 each (128 thr x 5), 90 chunks per b.
#define CB_ITERS_ 5
#define CHUNK4_ (THR_ * CB_ITERS_)   // 640
#define CH_PER_B_ (QC4_ / CHUNK4_)   // 90
#define NCHUNKS_ (CH_PER_B_ * B_)    // 11520

// Scratch (no device mallocs; zero-initialized, self-resetting per run)
__device__ float g_partial[NJOBS_];
__device__ int   g_idx[B_ * 2];
__device__ float g_w[B_ * 2];
__device__ unsigned int g_cnt[B_];            // probs-job arrivals per b (0..32)
__device__ volatile unsigned int g_flag[B_];  // gate published
__device__ unsigned int g_ccnt[B_];           // combine-chunk completions per b

// L2-only sector-granular load
__device__ __forceinline__ float ldcg(const float* p) {
    float v;
    asm volatile("ld.global.cg.f32 %0, [%1];" : "=f"(v) : "l"(p));
    return v;
}

// Gate for one b: runs on a single thread after all 32 partials are written.
__device__ void run_gate(int b,
                         const float* __restrict__ W1,
                         const float* __restrict__ b1,
                         const float* __restrict__ W2,
                         const float* __restrict__ b2,
                         float* __restrict__ out) {
    float p[E_];
    #pragma unroll
    for (int e = 0; e < E_; e++) {
        float t = 0.0f;
        #pragma unroll
        for (int s = 0; s < SPLIT_; s++)
            t += g_partial[b * 32 + e * SPLIT_ + s];
        float m = t * (1.0f / (float)Q_);
        p[e] = 1.0f / (1.0f + expf(-m));
    }

    float h[H_];
    #pragma unroll
    for (int j = 0; j < H_; j++) {
        float a = b1[j];
        #pragma unroll
        for (int e = 0; e < E_; e++) a += p[e] * W1[e * H_ + j];
        h[j] = fmaxf(a, 0.0f);
    }

    float z[E_];
    #pragma unroll
    for (int e = 0; e < E_; e++) {
        float a = b2[e];
        #pragma unroll
        for (int j = 0; j < H_; j++) a += h[j] * W2[j * E_ + e];
        z[e] = a;
    }

    float m = fmaxf(fmaxf(z[0], z[1]), fmaxf(z[2], z[3]));
    float w[E_], s = 0.0f;
    #pragma unroll
    for (int e = 0; e < E_; e++) { w[e] = expf(z[e] - m); s += w[e]; }
    float inv = 1.0f / s;
    #pragma unroll
    for (int e = 0; e < E_; e++) w[e] *= inv;

    int i0 = 0;
    #pragma unroll
    for (int e = 1; e < E_; e++) if (w[e] > w[i0]) i0 = e;
    int i1 = -1;
    #pragma unroll
    for (int e = 0; e < E_; e++) {
        if (e == i0) continue;
        if (i1 < 0 || w[e] > w[i1]) i1 = e;
    }

    float ms = w[i0] + w[i1];
    float rn = 1.0f / (ms + 1e-8f);
    float n0 = w[i0] * rn;
    float n1 = w[i1] * rn;

    g_idx[b * 2 + 0] = i0;
    g_idx[b * 2 + 1] = i1;
    g_w[b * 2 + 0] = n0;
    g_w[b * 2 + 1] = n1;

    // Tails: [combined | final_pred | norm_w | expert_probs | top_idx]
    float* fp = out + (size_t)B_ * QC_;
    float* nw = fp + B_;
    float* ep = nw + B_ * E_;
    float* ti = ep + B_ * E_;
    fp[b] = n0 * p[i0] + n1 * p[i1];
    #pragma unroll
    for (int e = 0; e < E_; e++) {
        nw[b * E_ + e] = (e == i0) ? n0 : ((e == i1) ? n1 : 0.0f);
        ep[b * E_ + e] = p[e];
    }
    ti[b * 2 + 0] = (float)i0;
    ti[b * 2 + 1] = (float)i1;

    __threadfence();      // publish gate results before flag
    g_flag[b] = 1u;
}

__global__ void __launch_bounds__(THR_, 8) moe_fused_kernel(
    const float* __restrict__ logits,
    const float* __restrict__ W1,
    const float* __restrict__ b1,
    const float* __restrict__ W2,
    const float* __restrict__ b2,
    float* __restrict__ out) {

    const int tid = threadIdx.x;
    const int blk = blockIdx.x;
    const int lane = tid & 31;
    const int wid  = tid >> 5;

    // ============ Phase 1: 4 probs jobs, loads front-batched =============
    float v[JOBS_PER_BLK_];
    int   jb[JOBS_PER_BLK_];
    #pragma unroll
    for (int jj = 0; jj < JOBS_PER_BLK_; jj++) {
        int j = blk + jj * NBLK_;
        int b = j >> 5;
        int sub = j & 31;
        int e = sub >> 3;
        int part = sub & 7;
        jb[jj] = j;
        int q = part * QCHUNK_ + tid;
        bool ok = (tid < QCHUNK_) && (q < Q_);
        const float* addr = logits + (size_t)(e * B_ + b) * QC_ + (size_t)q * C_;
        v[jj] = ok ? ldcg(addr) : 0.0f;
    }

    // reduce each job (shuffles independent -> ILP)
    #pragma unroll
    for (int jj = 0; jj < JOBS_PER_BLK_; jj++) {
        #pragma unroll
        for (int o = 16; o > 0; o >>= 1)
            v[jj] += __shfl_down_sync(0xffffffffu, v[jj], o);
    }

    __shared__ float ws[JOBS_PER_BLK_][4];
    if (lane == 0) {
        #pragma unroll
        for (int jj = 0; jj < JOBS_PER_BLK_; jj++) ws[jj][wid] = v[jj];
    }
    __syncthreads();

    if (tid == 0) {
        #pragma unroll
        for (int jj = 0; jj < JOBS_PER_BLK_; jj++) {
            g_partial[jb[jj]] = ws[jj][0] + ws[jj][1] + ws[jj][2] + ws[jj][3];
        }
        __threadfence();   // partials visible before arrivals
        #pragma unroll
        for (int jj = 0; jj < JOBS_PER_BLK_; jj++) {
            int b = jb[jj] >> 5;
            unsigned int n = atomicAdd(&g_cnt[b], 1u);
            if (n == 31u) {           // last arrival for this b -> gate
                g_cnt[b] = 0u;        // reset for next replay
                run_gate(b, W1, b1, W2, b2, out);
            }
        }
    }

    // ============ Phase 2: per-b pipelined streaming combine =============
    const float4* src = (const float4*)logits;
    float4* dst = (float4*)out;

    for (int c = blk; c < NCHUNKS_; c += NBLK_) {
        int b = c / CH_PER_B_;
        int seg = c - b * CH_PER_B_;

        if (tid == 0) {
            long guard = 0;
            while (g_flag[b] == 0u && guard < (1L << 26)) {
                __nanosleep(64);
                guard++;
            }
        }
        __syncthreads();
        __threadfence();   // acquire: see g_idx/g_w written by gate thread

        int i0 = g_idx[b * 2 + 0];
        int i1 = g_idx[b * 2 + 1];
        float w0 = g_w[b * 2 + 0];
        float w1 = g_w[b * 2 + 1];

        int base = seg * CHUNK4_ + tid;
        const float4* a0 = src + (size_t)(i0 * B_ + b) * QC4_ + base;
        const float4* a1 = src + (size_t)(i1 * B_ + b) * QC4_ + base;
        float4* o = dst + (size_t)b * QC4_ + base;

        float4 x[CB_ITERS_], y[CB_ITERS_];
        #pragma unroll
        for (int k = 0; k < CB_ITERS_; k++)
            x[k] = __ldcs(a0 + k * THR_);
        #pragma unroll
        for (int k = 0; k < CB_ITERS_; k++)
            y[k] = __ldcs(a1 + k * THR_);

        #pragma unroll
        for (int k = 0; k < CB_ITERS_; k++) {
            float4 r;
            r.x = w0 * x[k].x + w1 * y[k].x;
            r.y = w0 * x[k].y + w1 * y[k].y;
            r.z = w0 * x[k].z + w1 * y[k].z;
            r.w = w0 * x[k].w + w1 * y[k].w;
            __stcs(o + k * THR_, r);
        }

        // Per-b completion count; last chunk resets state for next replay.
        // Safe: all 90 spin-checks for b have already passed by now.
        if (tid == 0) {
            unsigned int n = atomicAdd(&g_ccnt[b], 1u);
            if (n == CH_PER_B_ - 1u) {
                g_ccnt[b] = 0u;
                g_flag[b] = 0u;
            }
        }
    }
}

extern "C" void kernel_launch(void* const* d_in, const int* in_sizes, int n_in,
                              void* d_out, int out_size) {
    const float* logits = (const float*)d_in[0];
    const float* W1     = (const float*)d_in[1];
    const float* b1     = (const float*)d_in[2];
    const float* W2     = (const float*)d_in[3];
    const float* b2     = (const float*)d_in[4];
    float* out = (float*)d_out;

    moe_fused_kernel<<<NBLK_, THR_>>>(logits, W1, b1, W2, b2, out);
}